// round 5
// baseline (speedup 1.0000x reference)
#include <cuda_runtime.h>
#include <cuda_bf16.h>
#include <cstddef>

// ---------------------------------------------------------------------------
// Problem constants
// ---------------------------------------------------------------------------
#define BB   8
#define NN   64
#define TT   (BB * NN * NN)      // 32768 tokens
#define DD   128
#define HH   4
#define DHH  32
#define LL   3
#define FFD  512

static __device__ float g_tok[TT * DD];   // token buffer  (16 MB)
static __device__ float g_q  [TT * DD];
static __device__ float g_k  [TT * DD];
static __device__ float g_v1 [TT * DD];
static __device__ float g_v2 [TT * DD];
static __device__ float g_o  [TT * DD];   // attention output
static __device__ float g_tmp[TT * DD];   // post-GEMM temp before LN
static __device__ float g_ff [TT * FFD];  // FFN hidden (64 MB)

// ---------------------------------------------------------------------------
// Embedding: tok[b,i,j,:] = node/edge/no_edge
// grid = 32768 blocks (one token), 128 threads (one channel each)
// ---------------------------------------------------------------------------
__global__ __launch_bounds__(128) void embed_kernel(
    const float* __restrict__ x, const float* __restrict__ ea,
    const int*   __restrict__ mask,                       // nonzero-word test
    const float* __restrict__ nW, const float* __restrict__ nb,
    const float* __restrict__ eW, const float* __restrict__ eb,
    const float* __restrict__ noe, float* __restrict__ tok)
{
    int t = blockIdx.x;
    int d = threadIdx.x;
    int b = t >> 12;
    int i = (t >> 6) & 63;
    int j = t & 63;

    float val;
    if (i == j) {
        val = nb[d];
        const float* xr = x + (size_t)(b * NN + i) * 16;
#pragma unroll
        for (int c = 0; c < 16; c++) val = fmaf(xr[c], nW[c * DD + d], val);
    } else if (mask[t] != 0) {
        val = eb[d];
        const float* er = ea + (size_t)t * 8;
#pragma unroll
        for (int c = 0; c < 8; c++) val = fmaf(er[c], eW[c * DD + d], val);
    } else {
        val = noe[d];
    }
    tok[(size_t)t * DD + d] = val;
}

// ---------------------------------------------------------------------------
// Tiled fp32 GEMM: C[M,Nc] = A[M,K] @ W[K,Nc] (+bias) (+relu)
// Block tile 128x128, BK=16, 256 threads, thread tile 8x8.
// ---------------------------------------------------------------------------
template <bool BIAS, bool RELU>
__global__ __launch_bounds__(256) void gemm_kernel(
    const float* __restrict__ A, const float* __restrict__ W,
    const float* __restrict__ bias, float* __restrict__ C,
    int M, int K, int Nc)
{
    __shared__ float As[16][132];   // A tile transposed, padded
    __shared__ float Bs[16][128];

    int tid  = threadIdx.x;
    int row0 = blockIdx.y * 128;
    int n0   = blockIdx.x * 128;

    int tx = tid & 15, ty = tid >> 4;
    int tm0 = ty * 8, tn0 = tx * 8;

    float acc[8][8];
#pragma unroll
    for (int i = 0; i < 8; i++)
#pragma unroll
        for (int j = 0; j < 8; j++) acc[i][j] = 0.f;

    int ar  = tid >> 2;   // 0..63 (A row within half-tile)
    int ac4 = tid & 3;    // float4 col within BK
    int br  = tid >> 5;   // 0..7  (B row within half-tile)
    int bc4 = tid & 31;   // float4 col within BN

    for (int k0 = 0; k0 < K; k0 += 16) {
#pragma unroll
        for (int rr = 0; rr < 2; rr++) {
            int m = ar + rr * 64;
            float4 a4 = *reinterpret_cast<const float4*>(
                &A[(size_t)(row0 + m) * K + k0 + ac4 * 4]);
            As[ac4 * 4 + 0][m] = a4.x;
            As[ac4 * 4 + 1][m] = a4.y;
            As[ac4 * 4 + 2][m] = a4.z;
            As[ac4 * 4 + 3][m] = a4.w;
        }
#pragma unroll
        for (int rr = 0; rr < 2; rr++) {
            int kk = br + rr * 8;
            *reinterpret_cast<float4*>(&Bs[kk][bc4 * 4]) =
                *reinterpret_cast<const float4*>(
                    &W[(size_t)(k0 + kk) * Nc + n0 + bc4 * 4]);
        }
        __syncthreads();
#pragma unroll
        for (int k = 0; k < 16; k++) {
            float a[8], bfr[8];
#pragma unroll
            for (int i = 0; i < 8; i++) a[i]   = As[k][tm0 + i];
#pragma unroll
            for (int j = 0; j < 8; j++) bfr[j] = Bs[k][tn0 + j];
#pragma unroll
            for (int i = 0; i < 8; i++)
#pragma unroll
                for (int j = 0; j < 8; j++)
                    acc[i][j] = fmaf(a[i], bfr[j], acc[i][j]);
        }
        __syncthreads();
    }

#pragma unroll
    for (int i = 0; i < 8; i++) {
        size_t m = (size_t)(row0 + tm0 + i);
#pragma unroll
        for (int j = 0; j < 8; j++) {
            int n = n0 + tn0 + j;
            float v = acc[i][j];
            if (BIAS) v += bias[n];
            if (RELU) v = fmaxf(v, 0.f);
            C[m * Nc + n] = v;
        }
    }
}

// ---------------------------------------------------------------------------
// Triangle attention. One CTA per (b,i) = blockIdx.x, 256 threads.
//   q_s[l][c]  = q[b,i,l,c]        (contiguous slab)
//   v1_s[l][c] = v1[b,i,l,c]
//   stream l: row[j][c] = k[b,l,j,c] / v2[b,l,j,c]  (contiguous slab per l)
//   S[h][l][j] = (1/sqrt(32)) * sum_d q_s[l][h*32+d] * row[j][h*32+d]
//   softmax over l, then o[b,i,j,c] = sum_l a[h][l][j] * v1_s[l][c] * row[j][c]
// SMEM: q 32K + v1 32K + S 64K + row (stride 129) 33K = 164096 B
// ---------------------------------------------------------------------------
#define ATTN_SMEM_FLOATS (8192 + 8192 + 16384 + 64 * 129)
#define ATTN_SMEM_BYTES  (ATTN_SMEM_FLOATS * 4)

__global__ __launch_bounds__(256) void attn_kernel(
    const float* __restrict__ q,  const float* __restrict__ kk,
    const float* __restrict__ v1, const float* __restrict__ v2,
    float* __restrict__ o)
{
    extern __shared__ float sm[];
    float* q_s  = sm;                 // [64][128]
    float* v1_s = sm + 8192;          // [64][128]
    float* S_s  = sm + 16384;         // [4][64][64]
    float* row  = sm + 32768;         // [64][129]

    int tid = threadIdx.x;
    int bi  = blockIdx.x;             // b*64 + i
    int b   = bi >> 6;

    // load q_s / v1_s (rows (i,l) are contiguous for fixed (b,i))
    const float* qbase  = q  + (size_t)bi * 8192;
    const float* v1base = v1 + (size_t)bi * 8192;
#pragma unroll
    for (int u = 0; u < 8; u++) {
        int f4 = tid + u * 256;
        *reinterpret_cast<float4*>(&q_s[f4 * 4]) =
            *reinterpret_cast<const float4*>(qbase + (size_t)f4 * 4);
        *reinterpret_cast<float4*>(&v1_s[f4 * 4]) =
            *reinterpret_cast<const float4*>(v1base + (size_t)f4 * 4);
    }

    float4 st[8];   // register-staged next l-row (double buffer via regs)

#define LDROW(src, l)                                                        \
    {                                                                        \
        const float* p_ = (src) + (size_t)(b * NN + (l)) * NN * DD;          \
        _Pragma("unroll")                                                    \
        for (int u = 0; u < 8; u++)                                          \
            st[u] = *reinterpret_cast<const float4*>(p_ + (tid + u*256)*4);  \
    }
#define STROW()                                                              \
    {                                                                        \
        _Pragma("unroll")                                                    \
        for (int u = 0; u < 8; u++) {                                        \
            int f4_ = tid + u * 256;                                         \
            int j_ = f4_ >> 5, c_ = (f4_ & 31) * 4;                          \
            float* d_ = &row[j_ * 129 + c_];                                 \
            d_[0] = st[u].x; d_[1] = st[u].y;                                \
            d_[2] = st[u].z; d_[3] = st[u].w;                                \
        }                                                                    \
    }

    // ---------------- S phase ----------------
    LDROW(kk, 0);
    __syncthreads();      // q_s/v1_s visible
    STROW();
    __syncthreads();

    {
        int h = tid >> 6, j = tid & 63;
        const float inv_scale = 0.17677669529663687f;   // 1/sqrt(32)
        for (int l = 0; l < 64; l++) {
            if (l < 63) LDROW(kk, l + 1);
            const float* qp = &q_s[l * 128 + h * 32];   // broadcast per warp
            const float* kp = &row[j * 129 + h * 32];   // conflict-free (stride 129)
            float dot = 0.f;
#pragma unroll
            for (int d = 0; d < 32; d++) dot = fmaf(qp[d], kp[d], dot);
            S_s[(h * 64 + l) * 64 + j] = dot * inv_scale;
            __syncthreads();
            if (l < 63) { STROW(); __syncthreads(); }
        }

        // softmax over l (each thread owns column (h,j))
        float m = -1e30f;
        for (int l = 0; l < 64; l++) m = fmaxf(m, S_s[(h * 64 + l) * 64 + j]);
        float ssum = 0.f;
        for (int l = 0; l < 64; l++) {
            float e = __expf(S_s[(h * 64 + l) * 64 + j] - m);
            S_s[(h * 64 + l) * 64 + j] = e;
            ssum += e;
        }
        float inv = 1.f / ssum;
        for (int l = 0; l < 64; l++) S_s[(h * 64 + l) * 64 + j] *= inv;
    }
    __syncthreads();

    // ---------------- O phase ----------------
    {
        int c  = tid & 127;     // channel
        int jh = tid >> 7;      // j-half (0/1)
        int h2 = c >> 5;
        float acc[32];
#pragma unroll
        for (int jj = 0; jj < 32; jj++) acc[jj] = 0.f;

        LDROW(v2, 0);
        STROW();
        __syncthreads();
        for (int l = 0; l < 64; l++) {
            if (l < 63) LDROW(v2, l + 1);
            float vc = v1_s[l * 128 + c];               // conflict-free
            const float* Sp = &S_s[(h2 * 64 + l) * 64 + jh * 32]; // broadcast
#pragma unroll
            for (int jj = 0; jj < 32; jj++) {
                float w = Sp[jj] * vc;
                acc[jj] = fmaf(w, row[(jh * 32 + jj) * 129 + c], acc[jj]);
            }
            __syncthreads();
            if (l < 63) { STROW(); __syncthreads(); }
        }
        float* ob = o + (size_t)bi * 8192;
#pragma unroll
        for (int jj = 0; jj < 32; jj++)
            ob[(size_t)(jh * 32 + jj) * 128 + c] = acc[jj];
    }
#undef LDROW
#undef STROW
}

// ---------------------------------------------------------------------------
// tok = LayerNorm(tok + x) * g + b   (per token; ddof=0, eps=1e-5)
// grid = 32768, 128 threads
// ---------------------------------------------------------------------------
__global__ __launch_bounds__(128) void add_ln_kernel(
    float* __restrict__ tok, const float* __restrict__ x,
    const float* __restrict__ g, const float* __restrict__ bta)
{
    __shared__ float red[4];
    int t = blockIdx.x;
    int c = threadIdx.x;
    size_t idx = (size_t)t * DD + c;

    float val = tok[idx] + x[idx];

    float s = val;
#pragma unroll
    for (int o_ = 16; o_ > 0; o_ >>= 1) s += __shfl_xor_sync(0xffffffffu, s, o_);
    if ((c & 31) == 0) red[c >> 5] = s;
    __syncthreads();
    float mean = (red[0] + red[1] + red[2] + red[3]) * (1.f / 128.f);
    __syncthreads();

    float d = val - mean;
    float s2 = d * d;
#pragma unroll
    for (int o_ = 16; o_ > 0; o_ >>= 1) s2 += __shfl_xor_sync(0xffffffffu, s2, o_);
    if ((c & 31) == 0) red[c >> 5] = s2;
    __syncthreads();
    float var = (red[0] + red[1] + red[2] + red[3]) * (1.f / 128.f);
    float rs  = rsqrtf(var + 1e-5f);

    tok[idx] = d * rs * g[c] + bta[c];
}

// ---------------------------------------------------------------------------
// out[b*N+i] = diag_token(b,i) . Wout + bout
// ---------------------------------------------------------------------------
__global__ __launch_bounds__(128) void out_kernel(
    const float* __restrict__ tok, const float* __restrict__ Wout,
    const float* __restrict__ bout, float* __restrict__ out)
{
    __shared__ float red[4];
    int bi = blockIdx.x;               // b*64 + i
    int c  = threadIdx.x;
    int token = bi * NN + (bi & 63);   // (b, i, i)

    float s = tok[(size_t)token * DD + c] * Wout[c];
#pragma unroll
    for (int o_ = 16; o_ > 0; o_ >>= 1) s += __shfl_xor_sync(0xffffffffu, s, o_);
    if ((c & 31) == 0) red[c >> 5] = s;
    __syncthreads();
    if (c == 0) out[bi] = red[0] + red[1] + red[2] + red[3] + bout[0];
}

// ---------------------------------------------------------------------------
// kernel_launch
// ---------------------------------------------------------------------------
extern "C" void kernel_launch(void* const* d_in, const int* in_sizes, int n_in,
                              void* d_out, int out_size)
{
    (void)in_sizes; (void)n_in; (void)out_size;

    const float* x    = (const float*)d_in[0];
    const float* ea   = (const float*)d_in[1];
    const int*   mask = (const int*)  d_in[2];   // bool -> int32/float32; nonzero test works for both
    const float* nW   = (const float*)d_in[3];
    const float* nb   = (const float*)d_in[4];
    const float* eW   = (const float*)d_in[5];
    const float* eb   = (const float*)d_in[6];
    const float* noe  = (const float*)d_in[7];
    const float* Wq   = (const float*)d_in[8];
    const float* Wk   = (const float*)d_in[9];
    const float* Wv1  = (const float*)d_in[10];
    const float* Wv2  = (const float*)d_in[11];
    const float* Wo   = (const float*)d_in[12];
    const float* bo   = (const float*)d_in[13];
    const float* ln1g = (const float*)d_in[14];
    const float* ln1b = (const float*)d_in[15];
    const float* W1   = (const float*)d_in[16];
    const float* b1   = (const float*)d_in[17];
    const float* W2   = (const float*)d_in[18];
    const float* b2   = (const float*)d_in[19];
    const float* ln2g = (const float*)d_in[20];
    const float* ln2b = (const float*)d_in[21];
    const float* Wout = (const float*)d_in[22];
    const float* bout = (const float*)d_in[23];

    // scratch pointers (symbol lookup is immediate, not stream-ordered)
    float *p_tok, *p_q, *p_k, *p_v1, *p_v2, *p_o, *p_tmp, *p_ff;
    cudaGetSymbolAddress((void**)&p_tok, g_tok);
    cudaGetSymbolAddress((void**)&p_q,   g_q);
    cudaGetSymbolAddress((void**)&p_k,   g_k);
    cudaGetSymbolAddress((void**)&p_v1,  g_v1);
    cudaGetSymbolAddress((void**)&p_v2,  g_v2);
    cudaGetSymbolAddress((void**)&p_o,   g_o);
    cudaGetSymbolAddress((void**)&p_tmp, g_tmp);
    cudaGetSymbolAddress((void**)&p_ff,  g_ff);

    cudaFuncSetAttribute(attn_kernel,
        cudaFuncAttributeMaxDynamicSharedMemorySize, ATTN_SMEM_BYTES);

    embed_kernel<<<TT, 128>>>(x, ea, mask, nW, nb, eW, eb, noe, p_tok);

    const dim3 g128(1, TT / 128), g512(4, TT / 128);

    for (int l = 0; l < LL; l++) {
        const float* wq = Wq  + (size_t)l * DD * DD;
        const float* wk = Wk  + (size_t)l * DD * DD;
        const float* w1v = Wv1 + (size_t)l * DD * DD;
        const float* w2v = Wv2 + (size_t)l * DD * DD;
        const float* wo = Wo  + (size_t)l * DD * DD;
        const float* bol = bo  + (size_t)l * DD;
        const float* g1 = ln1g + (size_t)l * DD;
        const float* bb1 = ln1b + (size_t)l * DD;
        const float* w1 = W1  + (size_t)l * DD * FFD;
        const float* bf1 = b1 + (size_t)l * FFD;
        const float* w2 = W2  + (size_t)l * FFD * DD;
        const float* bf2 = b2 + (size_t)l * DD;
        const float* g2 = ln2g + (size_t)l * DD;
        const float* bb2 = ln2b + (size_t)l * DD;

        gemm_kernel<false, false><<<g128, 256>>>(p_tok, wq,  nullptr, p_q,  TT, DD, DD);
        gemm_kernel<false, false><<<g128, 256>>>(p_tok, wk,  nullptr, p_k,  TT, DD, DD);
        gemm_kernel<false, false><<<g128, 256>>>(p_tok, w1v, nullptr, p_v1, TT, DD, DD);
        gemm_kernel<false, false><<<g128, 256>>>(p_tok, w2v, nullptr, p_v2, TT, DD, DD);

        attn_kernel<<<BB * NN, 256, ATTN_SMEM_BYTES>>>(p_q, p_k, p_v1, p_v2, p_o);

        gemm_kernel<true, false><<<g128, 256>>>(p_o, wo, bol, p_tmp, TT, DD, DD);
        add_ln_kernel<<<TT, 128>>>(p_tok, p_tmp, g1, bb1);

        gemm_kernel<true, true ><<<g512, 256>>>(p_tok, w1, bf1, p_ff,  TT, DD,  FFD);
        gemm_kernel<true, false><<<g128, 256>>>(p_ff,  w2, bf2, p_tmp, TT, FFD, DD);
        add_ln_kernel<<<TT, 128>>>(p_tok, p_tmp, g2, bb2);
    }

    out_kernel<<<BB * NN, 128>>>(p_tok, Wout, bout, (float*)d_out);
}

// round 7
// speedup vs baseline: 1.4559x; 1.4559x over previous
#include <cuda_runtime.h>
#include <cuda_bf16.h>
#include <cstddef>

// ---------------------------------------------------------------------------
// Problem constants
// ---------------------------------------------------------------------------
#define BB   8
#define NN   64
#define TT   (BB * NN * NN)      // 32768 tokens
#define DD   128
#define HH   4
#define DHH  32
#define LL   3
#define FFD  512

// QKV offsets inside fused 512-wide projection
#define Q_OFF   0
#define K_OFF   128
#define V1_OFF  256
#define V2_OFF  384

static __device__ float g_tok [TT * DD];    // token buffer       (16 MB)
static __device__ float g_big [TT * FFD];   // QKV fused / FFN hidden (64 MB)
static __device__ float g_o   [TT * DD];    // attention output   (16 MB)
static __device__ float g_tmp [TT * DD];    // post-GEMM temp     (16 MB)
static __device__ float g_wpk [LL * DD * 4 * DD];  // packed QKV weights (0.8 MB)

// ---------------------------------------------------------------------------
// Pack Wq|Wk|Wv1|Wv2 -> wpack[l][k][512]
// grid = L*128 (one (l,k) row), 512 threads
// ---------------------------------------------------------------------------
__global__ __launch_bounds__(512) void pack_w_kernel(
    const float* __restrict__ Wq, const float* __restrict__ Wk,
    const float* __restrict__ Wv1, const float* __restrict__ Wv2,
    float* __restrict__ wpk)
{
    int lk = blockIdx.x;           // l*128 + k
    int l  = lk >> 7;
    int k  = lk & 127;
    int n  = threadIdx.x;          // 0..511
    int c  = n & 127;
    const float* src;
    switch (n >> 7) {
        case 0:  src = Wq;  break;
        case 1:  src = Wk;  break;
        case 2:  src = Wv1; break;
        default: src = Wv2; break;
    }
    wpk[(size_t)lk * 512 + n] = src[(size_t)l * DD * DD + k * DD + c];
}

// ---------------------------------------------------------------------------
// Embedding: tok[b,i,j,:] = node/edge/no_edge
// ---------------------------------------------------------------------------
__global__ __launch_bounds__(128) void embed_kernel(
    const float* __restrict__ x, const float* __restrict__ ea,
    const int*   __restrict__ mask,                       // nonzero-word test
    const float* __restrict__ nW, const float* __restrict__ nb,
    const float* __restrict__ eW, const float* __restrict__ eb,
    const float* __restrict__ noe, float* __restrict__ tok)
{
    int t = blockIdx.x;
    int d = threadIdx.x;
    int b = t >> 12;
    int i = (t >> 6) & 63;
    int j = t & 63;

    float val;
    if (i == j) {
        val = nb[d];
        const float* xr = x + (size_t)(b * NN + i) * 16;
#pragma unroll
        for (int c = 0; c < 16; c++) val = fmaf(xr[c], nW[c * DD + d], val);
    } else if (mask[t] != 0) {
        val = eb[d];
        const float* er = ea + (size_t)t * 8;
#pragma unroll
        for (int c = 0; c < 8; c++) val = fmaf(er[c], eW[c * DD + d], val);
    } else {
        val = noe[d];
    }
    tok[(size_t)t * DD + d] = val;
}

// ---------------------------------------------------------------------------
// Tiled fp32 GEMM: C[M,Nc] = A[M,K] @ W[K,Nc] (+bias) (+relu)
// Block tile 64(M) x 128(N), BK=16, 128 threads, 8x8 thread tile.
// Double-buffered SMEM, 1 __syncthreads per k-step.
// ---------------------------------------------------------------------------
template <bool BIAS, bool RELU>
__global__ __launch_bounds__(128) void gemm_kernel(
    const float* __restrict__ A, const float* __restrict__ W,
    const float* __restrict__ bias, float* __restrict__ C,
    int M, int K, int Nc)
{
    __shared__ float As[2][16][68];    // A transposed [k][m], padded
    __shared__ float Bs[2][16][128];

    int tid  = threadIdx.x;
    int row0 = blockIdx.y * 64;
    int n0   = blockIdx.x * 128;

    int tx = tid & 15, ty = tid >> 4;  // 16 x 8
    int tm0 = ty * 8, tn0 = tx * 8;

    float acc[8][8];
#pragma unroll
    for (int i = 0; i < 8; i++)
#pragma unroll
        for (int j = 0; j < 8; j++) acc[i][j] = 0.f;

    int ar  = tid >> 2;   // 0..31 (A row within half-tile)
    int ac4 = tid & 3;    // float4 col within BK
    int br  = tid >> 5;   // 0..3
    int bc4 = tid & 31;   // float4 col within BN

    float4 areg[2], breg[4];
    const int NIT = K >> 4;

    // prologue: load k-tile 0
#pragma unroll
    for (int rr = 0; rr < 2; rr++)
        areg[rr] = *reinterpret_cast<const float4*>(
            &A[(size_t)(row0 + ar + rr * 32) * K + ac4 * 4]);
#pragma unroll
    for (int rr = 0; rr < 4; rr++)
        breg[rr] = *reinterpret_cast<const float4*>(
            &W[(size_t)(br + rr * 4) * Nc + n0 + bc4 * 4]);
#pragma unroll
    for (int rr = 0; rr < 2; rr++) {
        int m = ar + rr * 32;
        As[0][ac4 * 4 + 0][m] = areg[rr].x;
        As[0][ac4 * 4 + 1][m] = areg[rr].y;
        As[0][ac4 * 4 + 2][m] = areg[rr].z;
        As[0][ac4 * 4 + 3][m] = areg[rr].w;
    }
#pragma unroll
    for (int rr = 0; rr < 4; rr++)
        *reinterpret_cast<float4*>(&Bs[0][br + rr * 4][bc4 * 4]) = breg[rr];
    __syncthreads();

    for (int it = 0; it < NIT; it++) {
        int cur = it & 1;
        if (it + 1 < NIT) {
            int k0 = (it + 1) << 4;
#pragma unroll
            for (int rr = 0; rr < 2; rr++)
                areg[rr] = *reinterpret_cast<const float4*>(
                    &A[(size_t)(row0 + ar + rr * 32) * K + k0 + ac4 * 4]);
#pragma unroll
            for (int rr = 0; rr < 4; rr++)
                breg[rr] = *reinterpret_cast<const float4*>(
                    &W[(size_t)(k0 + br + rr * 4) * Nc + n0 + bc4 * 4]);
        }
#pragma unroll
        for (int k = 0; k < 16; k++) {
            float a[8], bfr[8];
#pragma unroll
            for (int i = 0; i < 8; i++) a[i]   = As[cur][k][tm0 + i];
#pragma unroll
            for (int j = 0; j < 8; j++) bfr[j] = Bs[cur][k][tn0 + j];
#pragma unroll
            for (int i = 0; i < 8; i++)
#pragma unroll
                for (int j = 0; j < 8; j++)
                    acc[i][j] = fmaf(a[i], bfr[j], acc[i][j]);
        }
        if (it + 1 < NIT) {
            int nxt = cur ^ 1;
#pragma unroll
            for (int rr = 0; rr < 2; rr++) {
                int m = ar + rr * 32;
                As[nxt][ac4 * 4 + 0][m] = areg[rr].x;
                As[nxt][ac4 * 4 + 1][m] = areg[rr].y;
                As[nxt][ac4 * 4 + 2][m] = areg[rr].z;
                As[nxt][ac4 * 4 + 3][m] = areg[rr].w;
            }
#pragma unroll
            for (int rr = 0; rr < 4; rr++)
                *reinterpret_cast<float4*>(&Bs[nxt][br + rr * 4][bc4 * 4]) = breg[rr];
        }
        __syncthreads();
    }

#pragma unroll
    for (int i = 0; i < 8; i++) {
        size_t m = (size_t)(row0 + tm0 + i);
        float out[8];
#pragma unroll
        for (int j = 0; j < 8; j++) {
            float v = acc[i][j];
            if (BIAS) v += bias[n0 + tn0 + j];
            if (RELU) v = fmaxf(v, 0.f);
            out[j] = v;
        }
        *reinterpret_cast<float4*>(&C[m * Nc + n0 + tn0])     =
            make_float4(out[0], out[1], out[2], out[3]);
        *reinterpret_cast<float4*>(&C[m * Nc + n0 + tn0 + 4]) =
            make_float4(out[4], out[5], out[6], out[7]);
    }
}

// ---------------------------------------------------------------------------
// Triangle attention. One CTA per (b,i), 256 threads.
// Reads q/k/v1/v2 from fused QKV buffer (stride 512).
// Two alternating row buffers -> ONE sync per streamed l-slice.
// SMEM: q 32K + v1 32K + S 64K + 2 x row(64x129) 66K = 197120 B
// ---------------------------------------------------------------------------
#define ATTN_SMEM_FLOATS (8192 + 8192 + 16384 + 2 * 64 * 129)
#define ATTN_SMEM_BYTES  (ATTN_SMEM_FLOATS * 4)

__global__ __launch_bounds__(256) void attn_kernel(
    const float* __restrict__ qkv, float* __restrict__ o)
{
    extern __shared__ float sm[];
    float* q_s  = sm;                 // [64][128]
    float* v1_s = sm + 8192;          // [64][128]
    float* S_s  = sm + 16384;         // [4][64][64]
    float* rbuf[2] = { sm + 32768, sm + 32768 + 64 * 129 };  // [64][129] x2

    int tid = threadIdx.x;
    int bi  = blockIdx.x;             // b*64 + i
    int b   = bi >> 6;

    // load q_s / v1_s from fused buffer: token (b,i,l) row, offsets 0 / 256
#pragma unroll
    for (int u = 0; u < 8; u++) {
        int f4 = tid + u * 256;       // 0..2047
        int l  = f4 >> 5, c4 = f4 & 31;
        size_t base = (size_t)(bi * 64 + l) * 512 + c4 * 4;
        *reinterpret_cast<float4*>(&q_s [f4 * 4]) =
            *reinterpret_cast<const float4*>(qkv + base + Q_OFF);
        *reinterpret_cast<float4*>(&v1_s[f4 * 4]) =
            *reinterpret_cast<const float4*>(qkv + base + V1_OFF);
    }

    float4 st[8];   // register-staged next l-slice

#define LDROW(off, l)                                                         \
    {                                                                         \
        _Pragma("unroll")                                                     \
        for (int u = 0; u < 8; u++) {                                         \
            int f4_ = tid + u * 256;                                          \
            int j_ = f4_ >> 5, c4_ = f4_ & 31;                                \
            st[u] = *reinterpret_cast<const float4*>(                         \
                qkv + (size_t)(b * 4096 + (l) * 64 + j_) * 512 + (off) + c4_*4);\
        }                                                                     \
    }
#define STROW(dst)                                                            \
    {                                                                         \
        _Pragma("unroll")                                                     \
        for (int u = 0; u < 8; u++) {                                         \
            int f4_ = tid + u * 256;                                          \
            int j_ = f4_ >> 5, c_ = (f4_ & 31) * 4;                           \
            float* d_ = &(dst)[j_ * 129 + c_];                                \
            d_[0] = st[u].x; d_[1] = st[u].y;                                 \
            d_[2] = st[u].z; d_[3] = st[u].w;                                 \
        }                                                                     \
    }

    // ---------------- S phase ----------------
    LDROW(K_OFF, 0);
    STROW(rbuf[0]);
    __syncthreads();      // q_s/v1_s/rbuf0 visible

    {
        int h = tid >> 6, j = tid & 63;
        const float inv_scale = 0.17677669529663687f;   // 1/sqrt(32)
        for (int l = 0; l < 64; l++) {
            if (l < 63) LDROW(K_OFF, l + 1);
            const float* qp = &q_s[l * 128 + h * 32];        // warp broadcast
            const float* kp = &rbuf[l & 1][j * 129 + h * 32];// conflict-free
            float dot = 0.f;
#pragma unroll
            for (int d = 0; d < 32; d++) dot = fmaf(qp[d], kp[d], dot);
            S_s[(h * 64 + l) * 64 + j] = dot * inv_scale;
            if (l < 63) STROW(rbuf[(l + 1) & 1]);
            __syncthreads();
        }

        // softmax over l (each thread owns its own column (h,j))
        float m = -1e30f;
        for (int l = 0; l < 64; l++) m = fmaxf(m, S_s[(h * 64 + l) * 64 + j]);
        float ssum = 0.f;
        for (int l = 0; l < 64; l++) {
            float e = __expf(S_s[(h * 64 + l) * 64 + j] - m);
            S_s[(h * 64 + l) * 64 + j] = e;
            ssum += e;
        }
        float inv = 1.f / ssum;
        for (int l = 0; l < 64; l++) S_s[(h * 64 + l) * 64 + j] *= inv;
    }

    // ---------------- O phase ----------------
    {
        int c  = tid & 127;     // channel
        int jh = tid >> 7;      // j-half (0/1)
        int h2 = c >> 5;
        float acc[32];
#pragma unroll
        for (int jj = 0; jj < 32; jj++) acc[jj] = 0.f;

        LDROW(V2_OFF, 0);
        STROW(rbuf[0]);
        __syncthreads();        // also orders softmax S_s writes before reads
        for (int l = 0; l < 64; l++) {
            if (l < 63) LDROW(V2_OFF, l + 1);
            float vc = v1_s[l * 128 + c];                         // conflict-free
            const float* Sp = &S_s[(h2 * 64 + l) * 64 + jh * 32]; // broadcast
            const float* rp = rbuf[l & 1];
#pragma unroll
            for (int jj = 0; jj < 32; jj++) {
                float w = Sp[jj] * vc;
                acc[jj] = fmaf(w, rp[(jh * 32 + jj) * 129 + c], acc[jj]);
            }
            if (l < 63) STROW(rbuf[(l + 1) & 1]);
            __syncthreads();
        }
        float* ob = o + (size_t)bi * 8192;
#pragma unroll
        for (int jj = 0; jj < 32; jj++)
            ob[(size_t)(jh * 32 + jj) * 128 + c] = acc[jj];
    }
#undef LDROW
#undef STROW
}

// ---------------------------------------------------------------------------
// tok = LayerNorm(tok + x) * g + b   (per token; ddof=0, eps=1e-5)
// ---------------------------------------------------------------------------
__global__ __launch_bounds__(128) void add_ln_kernel(
    float* __restrict__ tok, const float* __restrict__ x,
    const float* __restrict__ g, const float* __restrict__ bta)
{
    __shared__ float red[4];
    int t = blockIdx.x;
    int c = threadIdx.x;
    size_t idx = (size_t)t * DD + c;

    float val = tok[idx] + x[idx];

    float s = val;
#pragma unroll
    for (int o_ = 16; o_ > 0; o_ >>= 1) s += __shfl_xor_sync(0xffffffffu, s, o_);
    if ((c & 31) == 0) red[c >> 5] = s;
    __syncthreads();
    float mean = (red[0] + red[1] + red[2] + red[3]) * (1.f / 128.f);
    __syncthreads();

    float d = val - mean;
    float s2 = d * d;
#pragma unroll
    for (int o_ = 16; o_ > 0; o_ >>= 1) s2 += __shfl_xor_sync(0xffffffffu, s2, o_);
    if ((c & 31) == 0) red[c >> 5] = s2;
    __syncthreads();
    float var = (red[0] + red[1] + red[2] + red[3]) * (1.f / 128.f);
    float rs  = rsqrtf(var + 1e-5f);

    tok[idx] = d * rs * g[c] + bta[c];
}

// ---------------------------------------------------------------------------
// out[b*N+i] = diag_token(b,i) . Wout + bout
// ---------------------------------------------------------------------------
__global__ __launch_bounds__(128) void out_kernel(
    const float* __restrict__ tok, const float* __restrict__ Wout,
    const float* __restrict__ bout, float* __restrict__ out)
{
    __shared__ float red[4];
    int bi = blockIdx.x;               // b*64 + i
    int c  = threadIdx.x;
    int token = bi * NN + (bi & 63);   // (b, i, i)

    float s = tok[(size_t)token * DD + c] * Wout[c];
#pragma unroll
    for (int o_ = 16; o_ > 0; o_ >>= 1) s += __shfl_xor_sync(0xffffffffu, s, o_);
    if ((c & 31) == 0) red[c >> 5] = s;
    __syncthreads();
    if (c == 0) out[bi] = red[0] + red[1] + red[2] + red[3] + bout[0];
}

// ---------------------------------------------------------------------------
// kernel_launch
// ---------------------------------------------------------------------------
extern "C" void kernel_launch(void* const* d_in, const int* in_sizes, int n_in,
                              void* d_out, int out_size)
{
    (void)in_sizes; (void)n_in; (void)out_size;

    const float* x    = (const float*)d_in[0];
    const float* ea   = (const float*)d_in[1];
    const int*   mask = (const int*)  d_in[2];
    const float* nW   = (const float*)d_in[3];
    const float* nb   = (const float*)d_in[4];
    const float* eW   = (const float*)d_in[5];
    const float* eb   = (const float*)d_in[6];
    const float* noe  = (const float*)d_in[7];
    const float* Wq   = (const float*)d_in[8];
    const float* Wk   = (const float*)d_in[9];
    const float* Wv1  = (const float*)d_in[10];
    const float* Wv2  = (const float*)d_in[11];
    const float* Wo   = (const float*)d_in[12];
    const float* bo   = (const float*)d_in[13];
    const float* ln1g = (const float*)d_in[14];
    const float* ln1b = (const float*)d_in[15];
    const float* W1   = (const float*)d_in[16];
    const float* b1   = (const float*)d_in[17];
    const float* W2   = (const float*)d_in[18];
    const float* b2   = (const float*)d_in[19];
    const float* ln2g = (const float*)d_in[20];
    const float* ln2b = (const float*)d_in[21];
    const float* Wout = (const float*)d_in[22];
    const float* bout = (const float*)d_in[23];

    float *p_tok, *p_big, *p_o, *p_tmp, *p_wpk;
    cudaGetSymbolAddress((void**)&p_tok, g_tok);
    cudaGetSymbolAddress((void**)&p_big, g_big);
    cudaGetSymbolAddress((void**)&p_o,   g_o);
    cudaGetSymbolAddress((void**)&p_tmp, g_tmp);
    cudaGetSymbolAddress((void**)&p_wpk, g_wpk);

    cudaFuncSetAttribute(attn_kernel,
        cudaFuncAttributeMaxDynamicSharedMemorySize, ATTN_SMEM_BYTES);

    pack_w_kernel<<<LL * DD, 512>>>(Wq, Wk, Wv1, Wv2, p_wpk);
    embed_kernel<<<TT, 128>>>(x, ea, mask, nW, nb, eW, eb, noe, p_tok);

    const dim3 gN128(1, TT / 64);   // Nc = 128
    const dim3 gN512(4, TT / 64);   // Nc = 512

    for (int l = 0; l < LL; l++) {
        const float* wqkv = p_wpk + (size_t)l * DD * 512;
        const float* wo   = Wo   + (size_t)l * DD * DD;
        const float* bol  = bo   + (size_t)l * DD;
        const float* g1   = ln1g + (size_t)l * DD;
        const float* bb1  = ln1b + (size_t)l * DD;
        const float* w1   = W1   + (size_t)l * DD * FFD;
        const float* bf1  = b1   + (size_t)l * FFD;
        const float* w2   = W2   + (size_t)l * FFD * DD;
        const float* bf2  = b2   + (size_t)l * DD;
        const float* g2   = ln2g + (size_t)l * DD;
        const float* bb2  = ln2b + (size_t)l * DD;

        // fused QKV projection: [TT,128] @ [128,512] -> g_big
        gemm_kernel<false, false><<<gN512, 128>>>(p_tok, wqkv, nullptr, p_big, TT, DD, 4 * DD);

        attn_kernel<<<BB * NN, 256, ATTN_SMEM_BYTES>>>(p_big, p_o);

        gemm_kernel<true, false><<<gN128, 128>>>(p_o, wo, bol, p_tmp, TT, DD, DD);
        add_ln_kernel<<<TT, 128>>>(p_tok, p_tmp, g1, bb1);

        gemm_kernel<true, true ><<<gN512, 128>>>(p_tok, w1, bf1, p_big, TT, DD,  FFD);
        gemm_kernel<true, false><<<gN128, 128>>>(p_big, w2, bf2, p_tmp, TT, FFD, DD);
        add_ln_kernel<<<TT, 128>>>(p_tok, p_tmp, g2, bb2);
    }

    out_kernel<<<BB * NN, 128>>>(p_tok, Wout, bout, (float*)d_out);
}

// round 12
// speedup vs baseline: 2.6162x; 1.7970x over previous
#include <cuda_runtime.h>
#include <cuda_bf16.h>
#include <cstddef>
#include <cstdint>

// ---------------------------------------------------------------------------
// Problem constants
// ---------------------------------------------------------------------------
#define BB   8
#define NN   64
#define TT   (BB * NN * NN)      // 32768 tokens
#define DD   128
#define HH   4
#define DHH  32
#define LL   3
#define FFD  512

// QKV offsets inside fused 512-wide projection
#define Q_OFF   0
#define K_OFF   128
#define V1_OFF  256
#define V2_OFF  384

static __device__ float g_tok [TT * DD];    // token buffer       (16 MB)
static __device__ float g_big [TT * FFD];   // QKV fused / FFN hidden (64 MB)
static __device__ float g_o   [TT * DD];    // attention output   (16 MB)
static __device__ float g_tmp [TT * DD];    // post-GEMM temp     (16 MB)
static __device__ float g_wpk [LL * DD * 4 * DD];  // packed QKV weights

// ---------------------------------------------------------------------------
// cp.async helpers
// ---------------------------------------------------------------------------
__device__ __forceinline__ void cp16(uint32_t dst, const void* src) {
    asm volatile("cp.async.cg.shared.global [%0], [%1], 16;\n"
                 :: "r"(dst), "l"(src) : "memory");
}
__device__ __forceinline__ void cp_commit() {
    asm volatile("cp.async.commit_group;\n" ::: "memory");
}
template <int N> __device__ __forceinline__ void cp_wait() {
    asm volatile("cp.async.wait_group %0;\n" :: "n"(N) : "memory");
}

// ---------------------------------------------------------------------------
// Pack Wq|Wk|Wv1|Wv2 -> wpack[l][k][512]
// ---------------------------------------------------------------------------
__global__ __launch_bounds__(512) void pack_w_kernel(
    const float* __restrict__ Wq, const float* __restrict__ Wk,
    const float* __restrict__ Wv1, const float* __restrict__ Wv2,
    float* __restrict__ wpk)
{
    int lk = blockIdx.x;           // l*128 + k
    int l  = lk >> 7;
    int k  = lk & 127;
    int n  = threadIdx.x;          // 0..511
    int c  = n & 127;
    const float* src;
    switch (n >> 7) {
        case 0:  src = Wq;  break;
        case 1:  src = Wk;  break;
        case 2:  src = Wv1; break;
        default: src = Wv2; break;
    }
    wpk[(size_t)lk * 512 + n] = src[(size_t)l * DD * DD + k * DD + c];
}

// ---------------------------------------------------------------------------
// Embedding: tok[b,i,j,:] = node/edge/no_edge
// ---------------------------------------------------------------------------
__global__ __launch_bounds__(128) void embed_kernel(
    const float* __restrict__ x, const float* __restrict__ ea,
    const int*   __restrict__ mask,
    const float* __restrict__ nW, const float* __restrict__ nb,
    const float* __restrict__ eW, const float* __restrict__ eb,
    const float* __restrict__ noe, float* __restrict__ tok)
{
    int t = blockIdx.x;
    int d = threadIdx.x;
    int b = t >> 12;
    int i = (t >> 6) & 63;
    int j = t & 63;

    float val;
    if (i == j) {
        val = nb[d];
        const float* xr = x + (size_t)(b * NN + i) * 16;
#pragma unroll
        for (int c = 0; c < 16; c++) val = fmaf(xr[c], nW[c * DD + d], val);
    } else if (mask[t] != 0) {
        val = eb[d];
        const float* er = ea + (size_t)t * 8;
#pragma unroll
        for (int c = 0; c < 8; c++) val = fmaf(er[c], eW[c * DD + d], val);
    } else {
        val = noe[d];
    }
    tok[(size_t)t * DD + d] = val;
}

// ---------------------------------------------------------------------------
// Tiled fp32 GEMM: C[M,Nc] = A[M,K] @ W[K,Nc] (+bias) (+relu)
// 64(M) x 128(N) tile, BK=16, 128 threads, 8x8 thread tile, double-buffered.
// ---------------------------------------------------------------------------
template <bool BIAS, bool RELU>
__global__ __launch_bounds__(128) void gemm_kernel(
    const float* __restrict__ A, const float* __restrict__ W,
    const float* __restrict__ bias, float* __restrict__ C,
    int M, int K, int Nc)
{
    __shared__ float As[2][16][68];
    __shared__ float Bs[2][16][128];

    int tid  = threadIdx.x;
    int row0 = blockIdx.y * 64;
    int n0   = blockIdx.x * 128;

    int tx = tid & 15, ty = tid >> 4;
    int tm0 = ty * 8, tn0 = tx * 8;

    float acc[8][8];
#pragma unroll
    for (int i = 0; i < 8; i++)
#pragma unroll
        for (int j = 0; j < 8; j++) acc[i][j] = 0.f;

    int ar  = tid >> 2;
    int ac4 = tid & 3;
    int br  = tid >> 5;
    int bc4 = tid & 31;

    float4 areg[2], breg[4];
    const int NIT = K >> 4;

#pragma unroll
    for (int rr = 0; rr < 2; rr++)
        areg[rr] = *reinterpret_cast<const float4*>(
            &A[(size_t)(row0 + ar + rr * 32) * K + ac4 * 4]);
#pragma unroll
    for (int rr = 0; rr < 4; rr++)
        breg[rr] = *reinterpret_cast<const float4*>(
            &W[(size_t)(br + rr * 4) * Nc + n0 + bc4 * 4]);
#pragma unroll
    for (int rr = 0; rr < 2; rr++) {
        int m = ar + rr * 32;
        As[0][ac4 * 4 + 0][m] = areg[rr].x;
        As[0][ac4 * 4 + 1][m] = areg[rr].y;
        As[0][ac4 * 4 + 2][m] = areg[rr].z;
        As[0][ac4 * 4 + 3][m] = areg[rr].w;
    }
#pragma unroll
    for (int rr = 0; rr < 4; rr++)
        *reinterpret_cast<float4*>(&Bs[0][br + rr * 4][bc4 * 4]) = breg[rr];
    __syncthreads();

    for (int it = 0; it < NIT; it++) {
        int cur = it & 1;
        if (it + 1 < NIT) {
            int k0 = (it + 1) << 4;
#pragma unroll
            for (int rr = 0; rr < 2; rr++)
                areg[rr] = *reinterpret_cast<const float4*>(
                    &A[(size_t)(row0 + ar + rr * 32) * K + k0 + ac4 * 4]);
#pragma unroll
            for (int rr = 0; rr < 4; rr++)
                breg[rr] = *reinterpret_cast<const float4*>(
                    &W[(size_t)(k0 + br + rr * 4) * Nc + n0 + bc4 * 4]);
        }
#pragma unroll
        for (int k = 0; k < 16; k++) {
            float a[8], bfr[8];
#pragma unroll
            for (int i = 0; i < 8; i++) a[i]   = As[cur][k][tm0 + i];
#pragma unroll
            for (int j = 0; j < 8; j++) bfr[j] = Bs[cur][k][tn0 + j];
#pragma unroll
            for (int i = 0; i < 8; i++)
#pragma unroll
                for (int j = 0; j < 8; j++)
                    acc[i][j] = fmaf(a[i], bfr[j], acc[i][j]);
        }
        if (it + 1 < NIT) {
            int nxt = cur ^ 1;
#pragma unroll
            for (int rr = 0; rr < 2; rr++) {
                int m = ar + rr * 32;
                As[nxt][ac4 * 4 + 0][m] = areg[rr].x;
                As[nxt][ac4 * 4 + 1][m] = areg[rr].y;
                As[nxt][ac4 * 4 + 2][m] = areg[rr].z;
                As[nxt][ac4 * 4 + 3][m] = areg[rr].w;
            }
#pragma unroll
            for (int rr = 0; rr < 4; rr++)
                *reinterpret_cast<float4*>(&Bs[nxt][br + rr * 4][bc4 * 4]) = breg[rr];
        }
        __syncthreads();
    }

#pragma unroll
    for (int i = 0; i < 8; i++) {
        size_t m = (size_t)(row0 + tm0 + i);
        float out[8];
#pragma unroll
        for (int j = 0; j < 8; j++) {
            float v = acc[i][j];
            if (BIAS) v += bias[n0 + tn0 + j];
            if (RELU) v = fmaxf(v, 0.f);
            out[j] = v;
        }
        *reinterpret_cast<float4*>(&C[m * Nc + n0 + tn0])     =
            make_float4(out[0], out[1], out[2], out[3]);
        *reinterpret_cast<float4*>(&C[m * Nc + n0 + tn0 + 4]) =
            make_float4(out[4], out[5], out[6], out[7]);
    }
}

// ---------------------------------------------------------------------------
// Fused flash-style triangle attention.
// CTA = (b, i-pair): grid 256, 512 threads. thread = (i_loc, h, j).
// Online softmax in registers; k/v2 slices streamed via triple-buffered
// cp.async (stride-132 rows, 16B-aligned); q/v1 rows via 6KB broadcast buf.
// ---------------------------------------------------------------------------
#define KV_STRIDE 132
#define KV_SLICE  (64 * KV_STRIDE)          // 8448 floats (one k or v2 slice)
#define KV_PAIR   (2 * KV_SLICE)            // 16896 floats
#define QV_SLICE  (4 * 128)                 // q(i0) v1(i0) q(i1) v1(i1)
#define ATTN_SMEM_FLOATS (3 * KV_PAIR + 3 * QV_SLICE)
#define ATTN_SMEM_BYTES  (ATTN_SMEM_FLOATS * 4)   // 208896 B

__global__ __launch_bounds__(512) void attn_kernel(
    const float* __restrict__ qkv, float* __restrict__ o)
{
    extern __shared__ float sm[];
    float* kv = sm;                        // [3][2][64][132]
    float* qv = sm + 3 * KV_PAIR;          // [3][4][128]

    const int tid = threadIdx.x;
    const int cta = blockIdx.x;            // b*32 + ipair
    const int b   = cta >> 5;
    const int i0  = (cta & 31) * 2;

    const int i_loc = tid >> 8;            // 0/1
    const int h     = (tid >> 6) & 3;
    const int j     = tid & 63;
    const int ig    = i0 + i_loc;

    auto issue = [&](int l, int bs) {
        uint32_t kvb = (uint32_t)__cvta_generic_to_shared(kv + bs * KV_PAIR);
        const float* src_base = qkv + (size_t)(b * 64 + l) * 64 * 512;
#pragma unroll
        for (int u = 0; u < 8; u++) {
            int f4 = tid + u * 512;        // 0..4095
            int sl = f4 >> 11;             // 0 = k, 1 = v2
            int g  = f4 & 2047;
            int jj = g >> 5, c4 = g & 31;
            uint32_t dst = kvb +
                (uint32_t)(sl * KV_SLICE + jj * KV_STRIDE + c4 * 4) * 4u;
            cp16(dst, src_base + (size_t)jj * 512 + 128 + sl * 256 + c4 * 4);
        }
        if (tid < 128) {                   // q/v1 rows for both i's
            int idx = tid >> 5, c4 = tid & 31;
            int il = idx >> 1, qsel = idx & 1;   // 0=q, 1=v1
            uint32_t dst = (uint32_t)__cvta_generic_to_shared(
                qv + bs * QV_SLICE + idx * 128 + c4 * 4);
            cp16(dst, qkv + (size_t)((b * 64 + i0 + il) * 64 + l) * 512
                          + qsel * 256 + c4 * 4);
        }
    };

    issue(0, 0); cp_commit();
    issue(1, 1); cp_commit();

    float4 acc[8];
#pragma unroll
    for (int u = 0; u < 8; u++) acc[u] = make_float4(0.f, 0.f, 0.f, 0.f);
    float mmax = -1e30f, ssum = 0.f;
    const float inv_scale = 0.17677669529663687f;   // 1/sqrt(32)

    for (int l = 0; l < 64; l++) {
        if (l < 63) cp_wait<1>(); else cp_wait<0>();
        __syncthreads();                    // slice l visible; slice l-1 readers done
        if (l + 2 < 64) { issue(l + 2, (l + 2) % 3); cp_commit(); }

        const float* kb   = kv + (l % 3) * KV_PAIR;
        const float* qvb  = qv + (l % 3) * QV_SLICE;
        const float4* kp  = (const float4*)(kb + j * KV_STRIDE + h * 32);
        const float4* v2p = (const float4*)(kb + KV_SLICE + j * KV_STRIDE + h * 32);
        const float4* qp  = (const float4*)(qvb + (i_loc * 2) * 128 + h * 32);
        const float4* v1p = (const float4*)(qvb + (i_loc * 2 + 1) * 128 + h * 32);

        float d0 = 0.f, d1 = 0.f, d2 = 0.f, d3 = 0.f;
#pragma unroll
        for (int u = 0; u < 8; u++) {
            float4 kq = kp[u], qq = qp[u];
            d0 = fmaf(qq.x, kq.x, d0); d1 = fmaf(qq.y, kq.y, d1);
            d2 = fmaf(qq.z, kq.z, d2); d3 = fmaf(qq.w, kq.w, d3);
        }
        float s = ((d0 + d1) + (d2 + d3)) * inv_scale;

        float p;
        if (s > mmax) {                     // new running max: rescale
            float corr = __expf(mmax - s);
            mmax = s;
            ssum *= corr;
#pragma unroll
            for (int u = 0; u < 8; u++) {
                acc[u].x *= corr; acc[u].y *= corr;
                acc[u].z *= corr; acc[u].w *= corr;
            }
            p = 1.f;
        } else {
            p = __expf(s - mmax);
        }
        ssum += p;

#pragma unroll
        for (int u = 0; u < 8; u++) {
            float4 a = v1p[u], v = v2p[u];
            acc[u].x = fmaf(p * a.x, v.x, acc[u].x);
            acc[u].y = fmaf(p * a.y, v.y, acc[u].y);
            acc[u].z = fmaf(p * a.z, v.z, acc[u].z);
            acc[u].w = fmaf(p * a.w, v.w, acc[u].w);
        }
    }

    float inv = 1.f / ssum;
    float4* ob = (float4*)(o + ((size_t)(b * 64 + ig) * 64 + j) * 128 + h * 32);
#pragma unroll
    for (int u = 0; u < 8; u++) {
        acc[u].x *= inv; acc[u].y *= inv; acc[u].z *= inv; acc[u].w *= inv;
        ob[u] = acc[u];
    }
}

// ---------------------------------------------------------------------------
// tok = LayerNorm(tok + x) * g + b
// ---------------------------------------------------------------------------
__global__ __launch_bounds__(128) void add_ln_kernel(
    float* __restrict__ tok, const float* __restrict__ x,
    const float* __restrict__ g, const float* __restrict__ bta)
{
    __shared__ float red[4];
    int t = blockIdx.x;
    int c = threadIdx.x;
    size_t idx = (size_t)t * DD + c;

    float val = tok[idx] + x[idx];

    float s = val;
#pragma unroll
    for (int o_ = 16; o_ > 0; o_ >>= 1) s += __shfl_xor_sync(0xffffffffu, s, o_);
    if ((c & 31) == 0) red[c >> 5] = s;
    __syncthreads();
    float mean = (red[0] + red[1] + red[2] + red[3]) * (1.f / 128.f);
    __syncthreads();

    float d = val - mean;
    float s2 = d * d;
#pragma unroll
    for (int o_ = 16; o_ > 0; o_ >>= 1) s2 += __shfl_xor_sync(0xffffffffu, s2, o_);
    if ((c & 31) == 0) red[c >> 5] = s2;
    __syncthreads();
    float var = (red[0] + red[1] + red[2] + red[3]) * (1.f / 128.f);
    float rs  = rsqrtf(var + 1e-5f);

    tok[idx] = d * rs * g[c] + bta[c];
}

// ---------------------------------------------------------------------------
// out[b*N+i] = diag_token(b,i) . Wout + bout
// ---------------------------------------------------------------------------
__global__ __launch_bounds__(128) void out_kernel(
    const float* __restrict__ tok, const float* __restrict__ Wout,
    const float* __restrict__ bout, float* __restrict__ out)
{
    __shared__ float red[4];
    int bi = blockIdx.x;
    int c  = threadIdx.x;
    int token = bi * NN + (bi & 63);

    float s = tok[(size_t)token * DD + c] * Wout[c];
#pragma unroll
    for (int o_ = 16; o_ > 0; o_ >>= 1) s += __shfl_xor_sync(0xffffffffu, s, o_);
    if ((c & 31) == 0) red[c >> 5] = s;
    __syncthreads();
    if (c == 0) out[bi] = red[0] + red[1] + red[2] + red[3] + bout[0];
}

// ---------------------------------------------------------------------------
// kernel_launch
// ---------------------------------------------------------------------------
extern "C" void kernel_launch(void* const* d_in, const int* in_sizes, int n_in,
                              void* d_out, int out_size)
{
    (void)in_sizes; (void)n_in; (void)out_size;

    const float* x    = (const float*)d_in[0];
    const float* ea   = (const float*)d_in[1];
    const int*   mask = (const int*)  d_in[2];
    const float* nW   = (const float*)d_in[3];
    const float* nb   = (const float*)d_in[4];
    const float* eW   = (const float*)d_in[5];
    const float* eb   = (const float*)d_in[6];
    const float* noe  = (const float*)d_in[7];
    const float* Wq   = (const float*)d_in[8];
    const float* Wk   = (const float*)d_in[9];
    const float* Wv1  = (const float*)d_in[10];
    const float* Wv2  = (const float*)d_in[11];
    const float* Wo   = (const float*)d_in[12];
    const float* bo   = (const float*)d_in[13];
    const float* ln1g = (const float*)d_in[14];
    const float* ln1b = (const float*)d_in[15];
    const float* W1   = (const float*)d_in[16];
    const float* b1   = (const float*)d_in[17];
    const float* W2   = (const float*)d_in[18];
    const float* b2   = (const float*)d_in[19];
    const float* ln2g = (const float*)d_in[20];
    const float* ln2b = (const float*)d_in[21];
    const float* Wout = (const float*)d_in[22];
    const float* bout = (const float*)d_in[23];

    float *p_tok, *p_big, *p_o, *p_tmp, *p_wpk;
    cudaGetSymbolAddress((void**)&p_tok, g_tok);
    cudaGetSymbolAddress((void**)&p_big, g_big);
    cudaGetSymbolAddress((void**)&p_o,   g_o);
    cudaGetSymbolAddress((void**)&p_tmp, g_tmp);
    cudaGetSymbolAddress((void**)&p_wpk, g_wpk);

    cudaFuncSetAttribute(attn_kernel,
        cudaFuncAttributeMaxDynamicSharedMemorySize, ATTN_SMEM_BYTES);

    pack_w_kernel<<<LL * DD, 512>>>(Wq, Wk, Wv1, Wv2, p_wpk);
    embed_kernel<<<TT, 128>>>(x, ea, mask, nW, nb, eW, eb, noe, p_tok);

    const dim3 gN128(1, TT / 64);   // Nc = 128
    const dim3 gN512(4, TT / 64);   // Nc = 512

    for (int l = 0; l < LL; l++) {
        const float* wqkv = p_wpk + (size_t)l * DD * 512;
        const float* wo   = Wo   + (size_t)l * DD * DD;
        const float* bol  = bo   + (size_t)l * DD;
        const float* g1   = ln1g + (size_t)l * DD;
        const float* bb1  = ln1b + (size_t)l * DD;
        const float* w1   = W1   + (size_t)l * DD * FFD;
        const float* bf1  = b1   + (size_t)l * FFD;
        const float* w2   = W2   + (size_t)l * FFD * DD;
        const float* bf2  = b2   + (size_t)l * DD;
        const float* g2   = ln2g + (size_t)l * DD;
        const float* bb2  = ln2b + (size_t)l * DD;

        // fused QKV projection: [TT,128] @ [128,512] -> g_big
        gemm_kernel<false, false><<<gN512, 128>>>(p_tok, wqkv, nullptr, p_big, TT, DD, 4 * DD);

        attn_kernel<<<BB * NN / 2, 512, ATTN_SMEM_BYTES>>>(p_big, p_o);

        gemm_kernel<true, false><<<gN128, 128>>>(p_o, wo, bol, p_tmp, TT, DD, DD);
        add_ln_kernel<<<TT, 128>>>(p_tok, p_tmp, g1, bb1);

        gemm_kernel<true, true ><<<gN512, 128>>>(p_tok, w1, bf1, p_big, TT, DD,  FFD);
        gemm_kernel<true, false><<<gN128, 128>>>(p_big, w2, bf2, p_tmp, TT, FFD, DD);
        add_ln_kernel<<<TT, 128>>>(p_tok, p_tmp, g2, bb2);
    }

    out_kernel<<<BB * NN, 128>>>(p_tok, Wout, bout, (float*)d_out);
}

// round 13
// speedup vs baseline: 2.8222x; 1.0788x over previous
#include <cuda_runtime.h>
#include <cuda_bf16.h>
#include <cstddef>
#include <cstdint>

// ---------------------------------------------------------------------------
// Problem constants
// ---------------------------------------------------------------------------
#define BB   8
#define NN   64
#define TT   (BB * NN * NN)      // 32768 tokens
#define DD   128
#define HH   4
#define DHH  32
#define LL   3
#define FFD  512

// QKV offsets inside fused 512-wide projection
#define Q_OFF   0
#define K_OFF   128
#define V1_OFF  256
#define V2_OFF  384

static __device__ float g_tok [TT * DD];    // token buffer       (16 MB)
static __device__ float g_big [TT * FFD];   // QKV fused / FFN hidden (64 MB)
static __device__ float g_o   [TT * DD];    // attention output   (16 MB)
static __device__ float g_wpk [LL * DD * 4 * DD];  // packed QKV weights

// ---------------------------------------------------------------------------
// cp.async helpers
// ---------------------------------------------------------------------------
__device__ __forceinline__ void cp16(uint32_t dst, const void* src) {
    asm volatile("cp.async.cg.shared.global [%0], [%1], 16;\n"
                 :: "r"(dst), "l"(src) : "memory");
}
__device__ __forceinline__ void cp_commit() {
    asm volatile("cp.async.commit_group;\n" ::: "memory");
}
template <int N> __device__ __forceinline__ void cp_wait() {
    asm volatile("cp.async.wait_group %0;\n" :: "n"(N) : "memory");
}

// ---------------------------------------------------------------------------
// packed f32x2 helpers (Blackwell FFMA2 path; exact fp32 semantics)
// ---------------------------------------------------------------------------
__device__ __forceinline__ unsigned long long splat2(float v) {
    unsigned long long r; uint32_t u = __float_as_uint(v);
    asm("mov.b64 %0, {%1, %1};" : "=l"(r) : "r"(u));
    return r;
}
__device__ __forceinline__ unsigned long long fma2(
    unsigned long long a, unsigned long long b, unsigned long long c) {
    unsigned long long d;
    asm("fma.rn.f32x2 %0, %1, %2, %3;" : "=l"(d) : "l"(a), "l"(b), "l"(c));
    return d;
}
__device__ __forceinline__ unsigned long long mul2(
    unsigned long long a, unsigned long long b) {
    unsigned long long d;
    asm("mul.rn.f32x2 %0, %1, %2;" : "=l"(d) : "l"(a), "l"(b));
    return d;
}
__device__ __forceinline__ float2 unpack2(unsigned long long v) {
    uint32_t lo, hi;
    asm("mov.b64 {%0, %1}, %2;" : "=r"(lo), "=r"(hi) : "l"(v));
    return make_float2(__uint_as_float(lo), __uint_as_float(hi));
}
__device__ __forceinline__ unsigned long long d2ll(double v) {
    return __double_as_longlong(v);
}

// ---------------------------------------------------------------------------
// Pack Wq|Wk|Wv1|Wv2 -> wpack[l][k][512]
// ---------------------------------------------------------------------------
__global__ __launch_bounds__(512) void pack_w_kernel(
    const float* __restrict__ Wq, const float* __restrict__ Wk,
    const float* __restrict__ Wv1, const float* __restrict__ Wv2,
    float* __restrict__ wpk)
{
    int lk = blockIdx.x;           // l*128 + k
    int l  = lk >> 7;
    int k  = lk & 127;
    int n  = threadIdx.x;          // 0..511
    int c  = n & 127;
    const float* src;
    switch (n >> 7) {
        case 0:  src = Wq;  break;
        case 1:  src = Wk;  break;
        case 2:  src = Wv1; break;
        default: src = Wv2; break;
    }
    wpk[(size_t)lk * 512 + n] = src[(size_t)l * DD * DD + k * DD + c];
}

// ---------------------------------------------------------------------------
// Embedding: tok[b,i,j,:] = node/edge/no_edge
// ---------------------------------------------------------------------------
__global__ __launch_bounds__(128) void embed_kernel(
    const float* __restrict__ x, const float* __restrict__ ea,
    const int*   __restrict__ mask,
    const float* __restrict__ nW, const float* __restrict__ nb,
    const float* __restrict__ eW, const float* __restrict__ eb,
    const float* __restrict__ noe, float* __restrict__ tok)
{
    int t = blockIdx.x;
    int d = threadIdx.x;
    int b = t >> 12;
    int i = (t >> 6) & 63;
    int j = t & 63;

    float val;
    if (i == j) {
        val = nb[d];
        const float* xr = x + (size_t)(b * NN + i) * 16;
#pragma unroll
        for (int c = 0; c < 16; c++) val = fmaf(xr[c], nW[c * DD + d], val);
    } else if (mask[t] != 0) {
        val = eb[d];
        const float* er = ea + (size_t)t * 8;
#pragma unroll
        for (int c = 0; c < 8; c++) val = fmaf(er[c], eW[c * DD + d], val);
    } else {
        val = noe[d];
    }
    tok[(size_t)t * DD + d] = val;
}

// ---------------------------------------------------------------------------
// Tiled fp32 GEMM with packed-f32x2 inner loop.
// MODE: 0 plain, 1 +bias, 2 +bias+relu, 3 +bias+residual+LayerNorm (Nc must
// be 128 and n0==0 for MODE 3: each CTA owns complete rows).
// 64(M) x 128(N) tile, BK=16, 128 threads, 8x8 thread tile, double-buffered.
// ---------------------------------------------------------------------------
template <int MODE>
__global__ __launch_bounds__(128) void gemm_kernel(
    const float* __restrict__ A, const float* __restrict__ W,
    const float* __restrict__ bias, float* __restrict__ C,
    int M, int K, int Nc,
    const float* __restrict__ resid,   // MODE 3: residual input (also = C)
    const float* __restrict__ lng,     // MODE 3: LN gamma
    const float* __restrict__ lnb)     // MODE 3: LN beta
{
    __shared__ float As[2][16][68];
    __shared__ float Bs[2][16][128];

    int tid  = threadIdx.x;
    int row0 = blockIdx.y * 64;
    int n0   = blockIdx.x * 128;

    int tx = tid & 15, ty = tid >> 4;
    int tm0 = ty * 8, tn0 = tx * 8;

    unsigned long long acc2[8][4];
#pragma unroll
    for (int i = 0; i < 8; i++)
#pragma unroll
        for (int j = 0; j < 4; j++) acc2[i][j] = 0ull;

    int ar  = tid >> 2;
    int ac4 = tid & 3;
    int br  = tid >> 5;
    int bc4 = tid & 31;

    float4 areg[2], breg[4];
    const int NIT = K >> 4;

#pragma unroll
    for (int rr = 0; rr < 2; rr++)
        areg[rr] = *reinterpret_cast<const float4*>(
            &A[(size_t)(row0 + ar + rr * 32) * K + ac4 * 4]);
#pragma unroll
    for (int rr = 0; rr < 4; rr++)
        breg[rr] = *reinterpret_cast<const float4*>(
            &W[(size_t)(br + rr * 4) * Nc + n0 + bc4 * 4]);
#pragma unroll
    for (int rr = 0; rr < 2; rr++) {
        int m = ar + rr * 32;
        As[0][ac4 * 4 + 0][m] = areg[rr].x;
        As[0][ac4 * 4 + 1][m] = areg[rr].y;
        As[0][ac4 * 4 + 2][m] = areg[rr].z;
        As[0][ac4 * 4 + 3][m] = areg[rr].w;
    }
#pragma unroll
    for (int rr = 0; rr < 4; rr++)
        *reinterpret_cast<float4*>(&Bs[0][br + rr * 4][bc4 * 4]) = breg[rr];
    __syncthreads();

    for (int it = 0; it < NIT; it++) {
        int cur = it & 1;
        if (it + 1 < NIT) {
            int k0 = (it + 1) << 4;
#pragma unroll
            for (int rr = 0; rr < 2; rr++)
                areg[rr] = *reinterpret_cast<const float4*>(
                    &A[(size_t)(row0 + ar + rr * 32) * K + k0 + ac4 * 4]);
#pragma unroll
            for (int rr = 0; rr < 4; rr++)
                breg[rr] = *reinterpret_cast<const float4*>(
                    &W[(size_t)(k0 + br + rr * 4) * Nc + n0 + bc4 * 4]);
        }
#pragma unroll
        for (int k = 0; k < 16; k++) {
            // A: 8 floats (16B-aligned: row stride 68*4=272B is 16B multiple)
            float4 al = *reinterpret_cast<const float4*>(&As[cur][k][tm0]);
            float4 ah = *reinterpret_cast<const float4*>(&As[cur][k][tm0 + 4]);
            // B: 4 packed pairs
            const double* bd = reinterpret_cast<const double*>(&Bs[cur][k][tn0]);
            unsigned long long b2r[4];
#pragma unroll
            for (int j = 0; j < 4; j++) b2r[j] = d2ll(bd[j]);

            unsigned long long a2s[8];
            a2s[0] = splat2(al.x); a2s[1] = splat2(al.y);
            a2s[2] = splat2(al.z); a2s[3] = splat2(al.w);
            a2s[4] = splat2(ah.x); a2s[5] = splat2(ah.y);
            a2s[6] = splat2(ah.z); a2s[7] = splat2(ah.w);
#pragma unroll
            for (int i = 0; i < 8; i++)
#pragma unroll
                for (int j = 0; j < 4; j++)
                    acc2[i][j] = fma2(a2s[i], b2r[j], acc2[i][j]);
        }
        if (it + 1 < NIT) {
            int nxt = cur ^ 1;
#pragma unroll
            for (int rr = 0; rr < 2; rr++) {
                int m = ar + rr * 32;
                As[nxt][ac4 * 4 + 0][m] = areg[rr].x;
                As[nxt][ac4 * 4 + 1][m] = areg[rr].y;
                As[nxt][ac4 * 4 + 2][m] = areg[rr].z;
                As[nxt][ac4 * 4 + 3][m] = areg[rr].w;
            }
#pragma unroll
            for (int rr = 0; rr < 4; rr++)
                *reinterpret_cast<float4*>(&Bs[nxt][br + rr * 4][bc4 * 4]) = breg[rr];
        }
        __syncthreads();
    }

    // ---------------- epilogue ----------------
    if (MODE == 3) {
        float bsv[8], gv[8], bv[8];
#pragma unroll
        for (int j = 0; j < 8; j++) {
            bsv[j] = bias[tn0 + j];
            gv[j]  = lng[tn0 + j];
            bv[j]  = lnb[tn0 + j];
        }
#pragma unroll
        for (int i = 0; i < 8; i++) {
            size_t m = (size_t)(row0 + tm0 + i);
            float out[8];
#pragma unroll
            for (int j = 0; j < 4; j++) {
                float2 p = unpack2(acc2[i][j]);
                out[2 * j] = p.x; out[2 * j + 1] = p.y;
            }
            const float4* rr4 = reinterpret_cast<const float4*>(
                &resid[m * 128 + tn0]);
            float4 r0 = rr4[0], r1 = rr4[1];
            out[0] += bsv[0] + r0.x; out[1] += bsv[1] + r0.y;
            out[2] += bsv[2] + r0.z; out[3] += bsv[3] + r0.w;
            out[4] += bsv[4] + r1.x; out[5] += bsv[5] + r1.y;
            out[6] += bsv[6] + r1.z; out[7] += bsv[7] + r1.w;

            float rsum = 0.f;
#pragma unroll
            for (int j = 0; j < 8; j++) rsum += out[j];
#pragma unroll
            for (int off = 1; off < 16; off <<= 1)
                rsum += __shfl_xor_sync(0xffffffffu, rsum, off);
            float mean = rsum * (1.f / 128.f);

            float sq = 0.f;
#pragma unroll
            for (int j = 0; j < 8; j++) {
                out[j] -= mean;
                sq += out[j] * out[j];
            }
#pragma unroll
            for (int off = 1; off < 16; off <<= 1)
                sq += __shfl_xor_sync(0xffffffffu, sq, off);
            float rs = rsqrtf(sq * (1.f / 128.f) + 1e-5f);

            float o8[8];
#pragma unroll
            for (int j = 0; j < 8; j++)
                o8[j] = out[j] * rs * gv[j] + bv[j];
            *reinterpret_cast<float4*>(&C[m * 128 + tn0]) =
                make_float4(o8[0], o8[1], o8[2], o8[3]);
            *reinterpret_cast<float4*>(&C[m * 128 + tn0 + 4]) =
                make_float4(o8[4], o8[5], o8[6], o8[7]);
        }
    } else {
#pragma unroll
        for (int i = 0; i < 8; i++) {
            size_t m = (size_t)(row0 + tm0 + i);
            float out[8];
#pragma unroll
            for (int j = 0; j < 4; j++) {
                float2 p = unpack2(acc2[i][j]);
                out[2 * j] = p.x; out[2 * j + 1] = p.y;
            }
#pragma unroll
            for (int j = 0; j < 8; j++) {
                if (MODE >= 1) out[j] += bias[n0 + tn0 + j];
                if (MODE == 2) out[j] = fmaxf(out[j], 0.f);
            }
            *reinterpret_cast<float4*>(&C[m * Nc + n0 + tn0]) =
                make_float4(out[0], out[1], out[2], out[3]);
            *reinterpret_cast<float4*>(&C[m * Nc + n0 + tn0 + 4]) =
                make_float4(out[4], out[5], out[6], out[7]);
        }
    }
}

// ---------------------------------------------------------------------------
// Fused flash-style triangle attention (f32x2 inner math).
// CTA = (b, i-pair): grid 256, 512 threads. thread = (i_loc, h, j).
// ---------------------------------------------------------------------------
#define KV_STRIDE 132
#define KV_SLICE  (64 * KV_STRIDE)
#define KV_PAIR   (2 * KV_SLICE)
#define QV_SLICE  (4 * 128)
#define ATTN_SMEM_FLOATS (3 * KV_PAIR + 3 * QV_SLICE)
#define ATTN_SMEM_BYTES  (ATTN_SMEM_FLOATS * 4)   // 208896 B

__global__ __launch_bounds__(512) void attn_kernel(
    const float* __restrict__ qkv, float* __restrict__ o)
{
    extern __shared__ float sm[];
    float* kv = sm;                        // [3][2][64][132]
    float* qv = sm + 3 * KV_PAIR;          // [3][4][128]

    const int tid = threadIdx.x;
    const int cta = blockIdx.x;            // b*32 + ipair
    const int b   = cta >> 5;
    const int i0  = (cta & 31) * 2;

    const int i_loc = tid >> 8;            // 0/1
    const int h     = (tid >> 6) & 3;
    const int j     = tid & 63;
    const int ig    = i0 + i_loc;

    auto issue = [&](int l, int bs) {
        uint32_t kvb = (uint32_t)__cvta_generic_to_shared(kv + bs * KV_PAIR);
        const float* src_base = qkv + (size_t)(b * 64 + l) * 64 * 512;
#pragma unroll
        for (int u = 0; u < 8; u++) {
            int f4 = tid + u * 512;        // 0..4095
            int sl = f4 >> 11;             // 0 = k, 1 = v2
            int g  = f4 & 2047;
            int jj = g >> 5, c4 = g & 31;
            uint32_t dst = kvb +
                (uint32_t)(sl * KV_SLICE + jj * KV_STRIDE + c4 * 4) * 4u;
            cp16(dst, src_base + (size_t)jj * 512 + 128 + sl * 256 + c4 * 4);
        }
        if (tid < 128) {                   // q/v1 rows for both i's
            int idx = tid >> 5, c4 = tid & 31;
            int il = idx >> 1, qsel = idx & 1;   // 0=q, 1=v1
            uint32_t dst = (uint32_t)__cvta_generic_to_shared(
                qv + bs * QV_SLICE + idx * 128 + c4 * 4);
            cp16(dst, qkv + (size_t)((b * 64 + i0 + il) * 64 + l) * 512
                          + qsel * 256 + c4 * 4);
        }
    };

    issue(0, 0); cp_commit();
    issue(1, 1); cp_commit();

    unsigned long long acc2[16];
#pragma unroll
    for (int u = 0; u < 16; u++) acc2[u] = 0ull;
    float mmax = -1e30f, ssum = 0.f;
    const float inv_scale = 0.17677669529663687f;   // 1/sqrt(32)

    for (int l = 0; l < 64; l++) {
        if (l < 63) cp_wait<1>(); else cp_wait<0>();
        __syncthreads();
        if (l + 2 < 64) { issue(l + 2, (l + 2) % 3); cp_commit(); }

        const float* kb  = kv + (l % 3) * KV_PAIR;
        const float* qvb = qv + (l % 3) * QV_SLICE;
        const double2* kp2  = (const double2*)(kb + j * KV_STRIDE + h * 32);
        const double2* v2p2 = (const double2*)(kb + KV_SLICE + j * KV_STRIDE + h * 32);
        const double2* qp2  = (const double2*)(qvb + (i_loc * 2) * 128 + h * 32);
        const double2* v1p2 = (const double2*)(qvb + (i_loc * 2 + 1) * 128 + h * 32);

        unsigned long long d2a = 0ull, d2b = 0ull;
#pragma unroll
        for (int u = 0; u < 8; u++) {
            double2 kd = kp2[u], qd = qp2[u];
            d2a = fma2(d2ll(qd.x), d2ll(kd.x), d2a);
            d2b = fma2(d2ll(qd.y), d2ll(kd.y), d2b);
        }
        float2 pa = unpack2(d2a), pb = unpack2(d2b);
        float s = ((pa.x + pa.y) + (pb.x + pb.y)) * inv_scale;

        float p;
        if (s > mmax) {
            float corr = __expf(mmax - s);
            mmax = s;
            ssum *= corr;
            unsigned long long c2 = splat2(corr);
#pragma unroll
            for (int u = 0; u < 16; u++) acc2[u] = mul2(acc2[u], c2);
            p = 1.f;
        } else {
            p = __expf(s - mmax);
        }
        ssum += p;

        unsigned long long p2 = splat2(p);
#pragma unroll
        for (int u = 0; u < 8; u++) {
            double2 ad = v1p2[u], vd = v2p2[u];
            acc2[2 * u]     = fma2(mul2(p2, d2ll(ad.x)), d2ll(vd.x), acc2[2 * u]);
            acc2[2 * u + 1] = fma2(mul2(p2, d2ll(ad.y)), d2ll(vd.y), acc2[2 * u + 1]);
        }
    }

    unsigned long long inv2 = splat2(1.f / ssum);
    double* ob2 = (double*)(o + ((size_t)(b * 64 + ig) * 64 + j) * 128 + h * 32);
#pragma unroll
    for (int u = 0; u < 16; u++)
        ob2[u] = __longlong_as_double(mul2(acc2[u], inv2));
}

// ---------------------------------------------------------------------------
// out[b*N+i] = diag_token(b,i) . Wout + bout
// ---------------------------------------------------------------------------
__global__ __launch_bounds__(128) void out_kernel(
    const float* __restrict__ tok, const float* __restrict__ Wout,
    const float* __restrict__ bout, float* __restrict__ out)
{
    __shared__ float red[4];
    int bi = blockIdx.x;
    int c  = threadIdx.x;
    int token = bi * NN + (bi & 63);

    float s = tok[(size_t)token * DD + c] * Wout[c];
#pragma unroll
    for (int o_ = 16; o_ > 0; o_ >>= 1) s += __shfl_xor_sync(0xffffffffu, s, o_);
    if ((c & 31) == 0) red[c >> 5] = s;
    __syncthreads();
    if (c == 0) out[bi] = red[0] + red[1] + red[2] + red[3] + bout[0];
}

// ---------------------------------------------------------------------------
// kernel_launch
// ---------------------------------------------------------------------------
extern "C" void kernel_launch(void* const* d_in, const int* in_sizes, int n_in,
                              void* d_out, int out_size)
{
    (void)in_sizes; (void)n_in; (void)out_size;

    const float* x    = (const float*)d_in[0];
    const float* ea   = (const float*)d_in[1];
    const int*   mask = (const int*)  d_in[2];
    const float* nW   = (const float*)d_in[3];
    const float* nb   = (const float*)d_in[4];
    const float* eW   = (const float*)d_in[5];
    const float* eb   = (const float*)d_in[6];
    const float* noe  = (const float*)d_in[7];
    const float* Wq   = (const float*)d_in[8];
    const float* Wk   = (const float*)d_in[9];
    const float* Wv1  = (const float*)d_in[10];
    const float* Wv2  = (const float*)d_in[11];
    const float* Wo   = (const float*)d_in[12];
    const float* bo   = (const float*)d_in[13];
    const float* ln1g = (const float*)d_in[14];
    const float* ln1b = (const float*)d_in[15];
    const float* W1   = (const float*)d_in[16];
    const float* b1   = (const float*)d_in[17];
    const float* W2   = (const float*)d_in[18];
    const float* b2   = (const float*)d_in[19];
    const float* ln2g = (const float*)d_in[20];
    const float* ln2b = (const float*)d_in[21];
    const float* Wout = (const float*)d_in[22];
    const float* bout = (const float*)d_in[23];

    float *p_tok, *p_big, *p_o, *p_wpk;
    cudaGetSymbolAddress((void**)&p_tok, g_tok);
    cudaGetSymbolAddress((void**)&p_big, g_big);
    cudaGetSymbolAddress((void**)&p_o,   g_o);
    cudaGetSymbolAddress((void**)&p_wpk, g_wpk);

    cudaFuncSetAttribute(attn_kernel,
        cudaFuncAttributeMaxDynamicSharedMemorySize, ATTN_SMEM_BYTES);

    pack_w_kernel<<<LL * DD, 512>>>(Wq, Wk, Wv1, Wv2, p_wpk);
    embed_kernel<<<TT, 128>>>(x, ea, mask, nW, nb, eW, eb, noe, p_tok);

    const dim3 gN128(1, TT / 64);   // Nc = 128
    const dim3 gN512(4, TT / 64);   // Nc = 512

    for (int l = 0; l < LL; l++) {
        const float* wqkv = p_wpk + (size_t)l * DD * 512;
        const float* wo   = Wo   + (size_t)l * DD * DD;
        const float* bol  = bo   + (size_t)l * DD;
        const float* g1   = ln1g + (size_t)l * DD;
        const float* bb1  = ln1b + (size_t)l * DD;
        const float* w1   = W1   + (size_t)l * DD * FFD;
        const float* bf1  = b1   + (size_t)l * FFD;
        const float* w2   = W2   + (size_t)l * FFD * DD;
        const float* bf2  = b2   + (size_t)l * DD;
        const float* g2   = ln2g + (size_t)l * DD;
        const float* bb2  = ln2b + (size_t)l * DD;

        // fused QKV projection: [TT,128] @ [128,512] -> g_big
        gemm_kernel<0><<<gN512, 128>>>(p_tok, wqkv, nullptr, p_big,
                                       TT, DD, 4 * DD, nullptr, nullptr, nullptr);

        attn_kernel<<<BB * NN / 2, 512, ATTN_SMEM_BYTES>>>(p_big, p_o);

        // tok = LN(tok + o@Wo + bo)   (fused epilogue)
        gemm_kernel<3><<<gN128, 128>>>(p_o, wo, bol, p_tok,
                                       TT, DD, DD, p_tok, g1, bb1);

        // FFN hidden: relu(tok@W1 + b1)
        gemm_kernel<2><<<gN512, 128>>>(p_tok, w1, bf1, p_big,
                                       TT, DD, FFD, nullptr, nullptr, nullptr);

        // tok = LN(tok + hidden@W2 + b2)   (fused epilogue)
        gemm_kernel<3><<<gN128, 128>>>(p_big, w2, bf2, p_tok,
                                       TT, FFD, DD, p_tok, g2, bb2);
    }

    out_kernel<<<BB * NN, 128>>>(p_tok, Wout, bout, (float*)d_out);
}